// round 1
// baseline (speedup 1.0000x reference)
#include <cuda_runtime.h>
#include <math.h>

#define N_ROWS 65536
#define IN_DIM 512
#define NEMB 4096
#define EDIM 64
#define TILE_M 128

// ---------------- scratch (device globals; no allocs allowed) ----------------
__device__ float  g_Qcodes[NEMB * IN_DIM];   // 8 MB: emb @ W_out + b_out
__device__ float  g_ehalf[NEMB];             // 0.5*||emb||^2
__device__ int    g_idx[N_ROWS];
__device__ int    g_counts[NEMB];
__device__ double g_loss;

// ---------------- helpers: packed fp32x2 FMA ----------------
__device__ __forceinline__ unsigned long long pack2(float x) {
    unsigned long long r; unsigned u = __float_as_uint(x);
    asm("mov.b64 %0, {%1, %1};" : "=l"(r) : "r"(u));
    return r;
}
__device__ __forceinline__ void fma2(unsigned long long& d, unsigned long long a, unsigned long long b) {
    asm("fma.rn.f32x2 %0, %1, %2, %0;" : "+l"(d) : "l"(a), "l"(b));
}

// ---------------- K_init: zero accumulators (graph replays!) ----------------
__global__ void k_init() {
    int t = blockIdx.x * blockDim.x + threadIdx.x;
    if (t < NEMB) g_counts[t] = 0;
    if (t == 0) g_loss = 0.0;
}

// ---------------- K_codes: Q_codes = emb @ W_out + b_out; ehalf -------------
__global__ void k_codes(const float* __restrict__ emb,
                        const float* __restrict__ W_out,
                        const float* __restrict__ b_out) {
    __shared__ float es[16 * 64];
    int tid = threadIdx.x;
    int cb = blockIdx.x * 16;
    for (int i = tid; i < 16 * 64; i += 256) es[i] = emb[(size_t)cb * 64 + i];
    __syncthreads();
    if (tid < 16) {
        float s = 0.f;
        for (int k = 0; k < 64; k++) { float e = es[tid * 64 + k]; s = fmaf(e, e, s); }
        g_ehalf[cb + tid] = 0.5f * s;
    }
    float accx[16], accy[16];
#pragma unroll
    for (int c = 0; c < 16; c++) { accx[c] = 0.f; accy[c] = 0.f; }
    int c0 = tid * 2;
    for (int k = 0; k < 64; k++) {
        float2 w = *(const float2*)&W_out[(size_t)k * 512 + c0];
#pragma unroll
        for (int c = 0; c < 16; c++) {
            float e = es[c * 64 + k];
            accx[c] = fmaf(e, w.x, accx[c]);
            accy[c] = fmaf(e, w.y, accy[c]);
        }
    }
    float2 b = *(const float2*)&b_out[c0];
#pragma unroll
    for (int c = 0; c < 16; c++) {
        float2 o = make_float2(accx[c] + b.x, accy[c] + b.y);
        *(float2*)&g_Qcodes[(size_t)(cb + c) * 512 + c0] = o;
    }
}

// ---------------- K_argmin: fused x = in@W_in+b_in, then argmin over codes --
// Block: 128 rows, 256 threads. Thread micro-tile: 8 rows x 8 codes (4 f32x2).
// Score = 0.5*||e||^2 - x.e  (same argmin as full squared distance).
__global__ __launch_bounds__(256, 2) void k_argmin(
    const float* __restrict__ inputs, const float* __restrict__ W_in,
    const float* __restrict__ b_in, const float* __restrict__ emb) {
    extern __shared__ float sm[];
    float* in_sT = sm;            // [64][128] phase A (k-transposed input chunk)
    float* w_s   = sm + 8192;     // [64][64]  phase A
    float* x_sT  = sm;            // [64][128] phase B (aliases in_sT)
    float* e_sT  = sm + 8192;     // [64][128] phase B
    float* eh    = sm + 16384;    // [128]
    float* red_v = sm + 8192;     // [128*16]  reduction (aliases e_sT, after last use)
    int*   red_i = (int*)(sm + 8192 + 2048);

    int tid = threadIdx.x;
    int rg = tid >> 4;            // 0..15 -> rows rg*8..rg*8+7
    int cg = tid & 15;            // 0..15 -> cols cg*8..cg*8+7 (or dims cg*4 in phase A)
    int rowbase = blockIdx.x * TILE_M;
    int lr = tid >> 1;            // loader row 0..127
    int loff = (tid & 1) * 32;    // loader k-offset

    // ---- Phase A: x[128][64] = inputs_tile @ W_in + b_in ----
    float accA[8][4];
#pragma unroll
    for (int i = 0; i < 8; i++)
#pragma unroll
        for (int j = 0; j < 4; j++) accA[i][j] = 0.f;

    for (int kc = 0; kc < 8; kc++) {
        __syncthreads();
        const float4* gi = (const float4*)(inputs + (size_t)(rowbase + lr) * 512 + kc * 64 + loff);
#pragma unroll
        for (int i = 0; i < 8; i++) {
            float4 v = gi[i];
            int k = loff + i * 4;
            in_sT[(k + 0) * 128 + lr] = v.x;
            in_sT[(k + 1) * 128 + lr] = v.y;
            in_sT[(k + 2) * 128 + lr] = v.z;
            in_sT[(k + 3) * 128 + lr] = v.w;
        }
        const float4* gw = (const float4*)(W_in + (size_t)kc * 4096);
        float4* w4 = (float4*)w_s;
        for (int i = tid; i < 1024; i += 256) w4[i] = gw[i];
        __syncthreads();
#pragma unroll 4
        for (int k = 0; k < 64; k++) {
            float4 xa = *(const float4*)&in_sT[k * 128 + rg * 8];
            float4 xb = *(const float4*)&in_sT[k * 128 + rg * 8 + 4];
            float4 w  = *(const float4*)&w_s[k * 64 + cg * 4];
            float xs[8] = {xa.x, xa.y, xa.z, xa.w, xb.x, xb.y, xb.z, xb.w};
            float ws[4] = {w.x, w.y, w.z, w.w};
#pragma unroll
            for (int i = 0; i < 8; i++)
#pragma unroll
                for (int j = 0; j < 4; j++)
                    accA[i][j] = fmaf(xs[i], ws[j], accA[i][j]);
        }
    }
    __syncthreads();   // in_sT dead; safe to overwrite with x_sT
    {
        float4 b4 = *(const float4*)&b_in[cg * 4];
        float bs[4] = {b4.x, b4.y, b4.z, b4.w};
#pragma unroll
        for (int j = 0; j < 4; j++)
#pragma unroll
            for (int i = 0; i < 8; i++)
                x_sT[(cg * 4 + j) * 128 + rg * 8 + i] = accA[i][j] + bs[j];
    }

    // ---- Phase B: argmin over 4096 codes in 32 chunks of 128 ----
    float best_v[8]; int best_i[8];
#pragma unroll
    for (int i = 0; i < 8; i++) { best_v[i] = 3.4e38f; best_i[i] = 0; }

    for (int cb = 0; cb < 32; cb++) {
        __syncthreads();   // prev chunk compute done before overwriting e_sT/eh
        const float4* ge = (const float4*)(emb + (size_t)(cb * 128 + lr) * 64 + loff);
#pragma unroll
        for (int i = 0; i < 8; i++) {
            float4 v = ge[i];
            int d = loff + i * 4;
            e_sT[(d + 0) * 128 + lr] = v.x;
            e_sT[(d + 1) * 128 + lr] = v.y;
            e_sT[(d + 2) * 128 + lr] = v.z;
            e_sT[(d + 3) * 128 + lr] = v.w;
        }
        if (tid < 128) eh[tid] = g_ehalf[cb * 128 + tid];
        __syncthreads();

        unsigned long long acc2[8][4];
#pragma unroll
        for (int i = 0; i < 8; i++)
#pragma unroll
            for (int j = 0; j < 4; j++) acc2[i][j] = 0ull;

#pragma unroll 2
        for (int d = 0; d < 64; d++) {
            float4 xa = *(const float4*)&x_sT[d * 128 + rg * 8];
            float4 xb = *(const float4*)&x_sT[d * 128 + rg * 8 + 4];
            const ulonglong2* ep = (const ulonglong2*)&e_sT[d * 128 + cg * 8];
            ulonglong2 E0 = ep[0], E1 = ep[1];
            unsigned long long X[8] = {pack2(xa.x), pack2(xa.y), pack2(xa.z), pack2(xa.w),
                                       pack2(xb.x), pack2(xb.y), pack2(xb.z), pack2(xb.w)};
#pragma unroll
            for (int i = 0; i < 8; i++) {
                fma2(acc2[i][0], X[i], E0.x);
                fma2(acc2[i][1], X[i], E0.y);
                fma2(acc2[i][2], X[i], E1.x);
                fma2(acc2[i][3], X[i], E1.y);
            }
        }
        int codebase = cb * 128 + cg * 8;
#pragma unroll
        for (int j = 0; j < 4; j++) {     // ascending code order -> first-min tie rule
            float ehl = eh[cg * 8 + 2 * j];
            float ehh = eh[cg * 8 + 2 * j + 1];
#pragma unroll
            for (int i = 0; i < 8; i++) {
                unsigned long long a = acc2[i][j];
                float lo = __uint_as_float((unsigned)(a & 0xffffffffull));
                float hi = __uint_as_float((unsigned)(a >> 32));
                float slo = ehl - lo;
                float shi = ehh - hi;
                if (slo < best_v[i]) { best_v[i] = slo; best_i[i] = codebase + 2 * j; }
                if (shi < best_v[i]) { best_v[i] = shi; best_i[i] = codebase + 2 * j + 1; }
            }
        }
    }
    __syncthreads();   // e_sT dead; reuse as reduction buffer
#pragma unroll
    for (int i = 0; i < 8; i++) {
        red_v[(rg * 8 + i) * 16 + cg] = best_v[i];
        red_i[(rg * 8 + i) * 16 + cg] = best_i[i];
    }
    __syncthreads();
    if (tid < 128) {
        float bv = red_v[tid * 16]; int bi = red_i[tid * 16];
#pragma unroll
        for (int j = 1; j < 16; j++) {
            float v = red_v[tid * 16 + j]; int id = red_i[tid * 16 + j];
            if (v < bv || (v == bv && id < bi)) { bv = v; bi = id; }
        }
        g_idx[rowbase + tid] = bi;
        atomicAdd(&g_counts[bi], 1);
    }
}

// ---------------- K_gather: out = in + (Q[idx]-in); loss partials -----------
__global__ void k_gather(const float* __restrict__ inputs, float* __restrict__ out) {
    const int nf4 = N_ROWS * IN_DIM / 4;
    float lsum = 0.f;
    const float4* in4 = (const float4*)inputs;
    float4* out4 = (float4*)out;
    const float4* q4p = (const float4*)g_Qcodes;
    for (int f = blockIdx.x * blockDim.x + threadIdx.x; f < nf4; f += gridDim.x * blockDim.x) {
        int row = f >> 7;
        int col = f & 127;
        int id = __ldg(&g_idx[row]);
        float4 q = q4p[(size_t)id * 128 + col];
        float4 a = in4[f];
        float dx = q.x - a.x, dy = q.y - a.y, dz = q.z - a.z, dw = q.w - a.w;
        out4[f] = make_float4(a.x + dx, a.y + dy, a.z + dz, a.w + dw); // STE emulated in fp32
        lsum = fmaf(dx, dx, fmaf(dy, dy, fmaf(dz, dz, fmaf(dw, dw, lsum))));
    }
    for (int o = 16; o > 0; o >>= 1) lsum += __shfl_down_sync(0xffffffffu, lsum, o);
    __shared__ float ws[8];
    int lane = threadIdx.x & 31, w = threadIdx.x >> 5;
    if (lane == 0) ws[w] = lsum;
    __syncthreads();
    if (w == 0) {
        float v = (lane < 8) ? ws[lane] : 0.f;
        for (int o = 4; o > 0; o >>= 1) v += __shfl_down_sync(0xffffffffu, v, o);
        if (lane == 0) atomicAdd(&g_loss, (double)v);
    }
}

// ---------------- K_final: loss + perplexity scalars ------------------------
__global__ void k_final(float* __restrict__ out, int out_size) {
    __shared__ float red[256];
    int tid = threadIdx.x;
    float s = 0.f;
    for (int i = tid; i < NEMB; i += 256) {
        float p = (float)g_counts[i] * (1.0f / 65536.0f);
        s += p * logf(p + 1e-10f);
    }
    red[tid] = s;
    __syncthreads();
    for (int st = 128; st > 0; st >>= 1) {
        if (tid < st) red[tid] += red[tid + st];
        __syncthreads();
    }
    if (tid == 0) {
        float m = (float)(g_loss * (1.0 / 33554432.0));   // mean((q-in)^2)
        out[out_size - 2] = m + 0.25f * m;                // q_latent + COMMIT*e_latent
        out[out_size - 1] = expf(-red[0]);
    }
}

// ---------------- launch ----------------
extern "C" void kernel_launch(void* const* d_in, const int* in_sizes, int n_in,
                              void* d_out, int out_size) {
    const float* inputs = (const float*)d_in[0];
    const float* emb    = (const float*)d_in[1];
    const float* W_in   = (const float*)d_in[2];
    const float* b_in   = (const float*)d_in[3];
    const float* W_out  = (const float*)d_in[4];
    const float* b_out  = (const float*)d_in[5];
    float* out = (float*)d_out;

    cudaFuncSetAttribute(k_argmin, cudaFuncAttributeMaxDynamicSharedMemorySize, 66048);

    k_init<<<16, 256>>>();
    k_codes<<<NEMB / 16, 256>>>(emb, W_out, b_out);
    k_argmin<<<N_ROWS / TILE_M, 256, 66048>>>(inputs, W_in, b_in, emb);
    k_gather<<<8192, 256>>>(inputs, out);
    k_final<<<1, 256>>>(out, out_size);
}

// round 2
// speedup vs baseline: 1.0001x; 1.0001x over previous
#include <cuda_runtime.h>
#include <math.h>

#define N_ROWS 65536
#define IN_DIM 512
#define NEMB 4096
#define EDIM 64
#define TILE_M 128

// ---------------- scratch (device globals; no allocs allowed) ----------------
__device__ float  g_Qcodes[NEMB * IN_DIM];   // 8 MB: emb @ W_out + b_out
__device__ float  g_ehalf[NEMB];             // 0.5*||emb||^2
__device__ int    g_idx[N_ROWS];
__device__ int    g_counts[NEMB];
__device__ double g_loss;

// ---------------- helpers: packed fp32x2 FMA ----------------
__device__ __forceinline__ unsigned long long pack2(float x) {
    unsigned long long r; unsigned u = __float_as_uint(x);
    asm("mov.b64 %0, {%1, %1};" : "=l"(r) : "r"(u));
    return r;
}
__device__ __forceinline__ void fma2(unsigned long long& d, unsigned long long a, unsigned long long b) {
    asm("fma.rn.f32x2 %0, %1, %2, %0;" : "+l"(d) : "l"(a), "l"(b));
}

// ---------------- K_init: zero accumulators (graph replays!) ----------------
__global__ void k_init() {
    int t = blockIdx.x * blockDim.x + threadIdx.x;
    if (t < NEMB) g_counts[t] = 0;
    if (t == 0) g_loss = 0.0;
}

// ---------------- K_codes: Q_codes = emb @ W_out + b_out; ehalf -------------
__global__ void k_codes(const float* __restrict__ emb,
                        const float* __restrict__ W_out,
                        const float* __restrict__ b_out) {
    __shared__ float es[16 * 64];
    int tid = threadIdx.x;
    int cb = blockIdx.x * 16;
    for (int i = tid; i < 16 * 64; i += 256) es[i] = emb[(size_t)cb * 64 + i];
    __syncthreads();
    if (tid < 16) {
        float s = 0.f;
        for (int k = 0; k < 64; k++) { float e = es[tid * 64 + k]; s = fmaf(e, e, s); }
        g_ehalf[cb + tid] = 0.5f * s;
    }
    float accx[16], accy[16];
#pragma unroll
    for (int c = 0; c < 16; c++) { accx[c] = 0.f; accy[c] = 0.f; }
    int c0 = tid * 2;
    for (int k = 0; k < 64; k++) {
        float2 w = *(const float2*)&W_out[(size_t)k * 512 + c0];
#pragma unroll
        for (int c = 0; c < 16; c++) {
            float e = es[c * 64 + k];
            accx[c] = fmaf(e, w.x, accx[c]);
            accy[c] = fmaf(e, w.y, accy[c]);
        }
    }
    float2 b = *(const float2*)&b_out[c0];
#pragma unroll
    for (int c = 0; c < 16; c++) {
        float2 o = make_float2(accx[c] + b.x, accy[c] + b.y);
        *(float2*)&g_Qcodes[(size_t)(cb + c) * 512 + c0] = o;
    }
}

// ---------------- K_argmin: fused x = in@W_in+b_in, then argmin over codes --
// Block: 128 rows, 256 threads. Thread micro-tile: 8 rows x 8 codes (4 f32x2).
// Score = 0.5*||e||^2 - x.e  (same argmin as full squared distance).
__global__ __launch_bounds__(256, 2) void k_argmin(
    const float* __restrict__ inputs, const float* __restrict__ W_in,
    const float* __restrict__ b_in, const float* __restrict__ emb) {
    extern __shared__ float sm[];
    float* in_sT = sm;            // [64][128] phase A (k-transposed input chunk)
    float* w_s   = sm + 8192;     // [64][64]  phase A
    float* x_sT  = sm;            // [64][128] phase B (aliases in_sT)
    float* e_sT  = sm + 8192;     // [64][128] phase B
    float* eh    = sm + 16384;    // [128]
    float* red_v = sm + 8192;     // [128*16]  reduction (aliases e_sT, after last use)
    int*   red_i = (int*)(sm + 8192 + 2048);

    int tid = threadIdx.x;
    int rg = tid >> 4;            // 0..15 -> rows rg*8..rg*8+7
    int cg = tid & 15;            // 0..15 -> cols cg*8..cg*8+7 (or dims cg*4 in phase A)
    int rowbase = blockIdx.x * TILE_M;
    int lr = tid >> 1;            // loader row 0..127
    int loff = (tid & 1) * 32;    // loader k-offset

    // ---- Phase A: x[128][64] = inputs_tile @ W_in + b_in ----
    float accA[8][4];
#pragma unroll
    for (int i = 0; i < 8; i++)
#pragma unroll
        for (int j = 0; j < 4; j++) accA[i][j] = 0.f;

    for (int kc = 0; kc < 8; kc++) {
        __syncthreads();
        const float4* gi = (const float4*)(inputs + (size_t)(rowbase + lr) * 512 + kc * 64 + loff);
#pragma unroll
        for (int i = 0; i < 8; i++) {
            float4 v = gi[i];
            int k = loff + i * 4;
            in_sT[(k + 0) * 128 + lr] = v.x;
            in_sT[(k + 1) * 128 + lr] = v.y;
            in_sT[(k + 2) * 128 + lr] = v.z;
            in_sT[(k + 3) * 128 + lr] = v.w;
        }
        const float4* gw = (const float4*)(W_in + (size_t)kc * 4096);
        float4* w4 = (float4*)w_s;
        for (int i = tid; i < 1024; i += 256) w4[i] = gw[i];
        __syncthreads();
#pragma unroll 4
        for (int k = 0; k < 64; k++) {
            float4 xa = *(const float4*)&in_sT[k * 128 + rg * 8];
            float4 xb = *(const float4*)&in_sT[k * 128 + rg * 8 + 4];
            float4 w  = *(const float4*)&w_s[k * 64 + cg * 4];
            float xs[8] = {xa.x, xa.y, xa.z, xa.w, xb.x, xb.y, xb.z, xb.w};
            float ws[4] = {w.x, w.y, w.z, w.w};
#pragma unroll
            for (int i = 0; i < 8; i++)
#pragma unroll
                for (int j = 0; j < 4; j++)
                    accA[i][j] = fmaf(xs[i], ws[j], accA[i][j]);
        }
    }
    __syncthreads();   // in_sT dead; safe to overwrite with x_sT
    {
        float4 b4 = *(const float4*)&b_in[cg * 4];
        float bs[4] = {b4.x, b4.y, b4.z, b4.w};
#pragma unroll
        for (int j = 0; j < 4; j++)
#pragma unroll
            for (int i = 0; i < 8; i++)
                x_sT[(cg * 4 + j) * 128 + rg * 8 + i] = accA[i][j] + bs[j];
    }

    // ---- Phase B: argmin over 4096 codes in 32 chunks of 128 ----
    float best_v[8]; int best_i[8];
#pragma unroll
    for (int i = 0; i < 8; i++) { best_v[i] = 3.4e38f; best_i[i] = 0; }

    for (int cb = 0; cb < 32; cb++) {
        __syncthreads();   // prev chunk compute done before overwriting e_sT/eh
        const float4* ge = (const float4*)(emb + (size_t)(cb * 128 + lr) * 64 + loff);
#pragma unroll
        for (int i = 0; i < 8; i++) {
            float4 v = ge[i];
            int d = loff + i * 4;
            e_sT[(d + 0) * 128 + lr] = v.x;
            e_sT[(d + 1) * 128 + lr] = v.y;
            e_sT[(d + 2) * 128 + lr] = v.z;
            e_sT[(d + 3) * 128 + lr] = v.w;
        }
        if (tid < 128) eh[tid] = g_ehalf[cb * 128 + tid];
        __syncthreads();

        unsigned long long acc2[8][4];
#pragma unroll
        for (int i = 0; i < 8; i++)
#pragma unroll
            for (int j = 0; j < 4; j++) acc2[i][j] = 0ull;

#pragma unroll 2
        for (int d = 0; d < 64; d++) {
            float4 xa = *(const float4*)&x_sT[d * 128 + rg * 8];
            float4 xb = *(const float4*)&x_sT[d * 128 + rg * 8 + 4];
            const ulonglong2* ep = (const ulonglong2*)&e_sT[d * 128 + cg * 8];
            ulonglong2 E0 = ep[0], E1 = ep[1];
            unsigned long long X[8] = {pack2(xa.x), pack2(xa.y), pack2(xa.z), pack2(xa.w),
                                       pack2(xb.x), pack2(xb.y), pack2(xb.z), pack2(xb.w)};
#pragma unroll
            for (int i = 0; i < 8; i++) {
                fma2(acc2[i][0], X[i], E0.x);
                fma2(acc2[i][1], X[i], E0.y);
                fma2(acc2[i][2], X[i], E1.x);
                fma2(acc2[i][3], X[i], E1.y);
            }
        }
        int codebase = cb * 128 + cg * 8;
#pragma unroll
        for (int j = 0; j < 4; j++) {     // ascending code order -> first-min tie rule
            float ehl = eh[cg * 8 + 2 * j];
            float ehh = eh[cg * 8 + 2 * j + 1];
#pragma unroll
            for (int i = 0; i < 8; i++) {
                unsigned long long a = acc2[i][j];
                float lo = __uint_as_float((unsigned)(a & 0xffffffffull));
                float hi = __uint_as_float((unsigned)(a >> 32));
                float slo = ehl - lo;
                float shi = ehh - hi;
                if (slo < best_v[i]) { best_v[i] = slo; best_i[i] = codebase + 2 * j; }
                if (shi < best_v[i]) { best_v[i] = shi; best_i[i] = codebase + 2 * j + 1; }
            }
        }
    }
    __syncthreads();   // e_sT dead; reuse as reduction buffer
#pragma unroll
    for (int i = 0; i < 8; i++) {
        red_v[(rg * 8 + i) * 16 + cg] = best_v[i];
        red_i[(rg * 8 + i) * 16 + cg] = best_i[i];
    }
    __syncthreads();
    if (tid < 128) {
        float bv = red_v[tid * 16]; int bi = red_i[tid * 16];
#pragma unroll
        for (int j = 1; j < 16; j++) {
            float v = red_v[tid * 16 + j]; int id = red_i[tid * 16 + j];
            if (v < bv || (v == bv && id < bi)) { bv = v; bi = id; }
        }
        g_idx[rowbase + tid] = bi;
        atomicAdd(&g_counts[bi], 1);
    }
}

// ---------------- K_gather: out = in + (Q[idx]-in); loss partials -----------
__global__ void k_gather(const float* __restrict__ inputs, float* __restrict__ out) {
    const int nf4 = N_ROWS * IN_DIM / 4;
    float lsum = 0.f;
    const float4* in4 = (const float4*)inputs;
    float4* out4 = (float4*)out;
    const float4* q4p = (const float4*)g_Qcodes;
    for (int f = blockIdx.x * blockDim.x + threadIdx.x; f < nf4; f += gridDim.x * blockDim.x) {
        int row = f >> 7;
        int col = f & 127;
        int id = __ldg(&g_idx[row]);
        float4 q = q4p[(size_t)id * 128 + col];
        float4 a = in4[f];
        float dx = q.x - a.x, dy = q.y - a.y, dz = q.z - a.z, dw = q.w - a.w;
        out4[f] = make_float4(a.x + dx, a.y + dy, a.z + dz, a.w + dw); // STE emulated in fp32
        lsum = fmaf(dx, dx, fmaf(dy, dy, fmaf(dz, dz, fmaf(dw, dw, lsum))));
    }
    for (int o = 16; o > 0; o >>= 1) lsum += __shfl_down_sync(0xffffffffu, lsum, o);
    __shared__ float ws[8];
    int lane = threadIdx.x & 31, w = threadIdx.x >> 5;
    if (lane == 0) ws[w] = lsum;
    __syncthreads();
    if (w == 0) {
        float v = (lane < 8) ? ws[lane] : 0.f;
        for (int o = 4; o > 0; o >>= 1) v += __shfl_down_sync(0xffffffffu, v, o);
        if (lane == 0) atomicAdd(&g_loss, (double)v);
    }
}

// ---------------- K_final: loss + perplexity scalars ------------------------
__global__ void k_final(float* __restrict__ out, int out_size) {
    __shared__ float red[256];
    int tid = threadIdx.x;
    float s = 0.f;
    for (int i = tid; i < NEMB; i += 256) {
        float p = (float)g_counts[i] * (1.0f / 65536.0f);
        s += p * logf(p + 1e-10f);
    }
    red[tid] = s;
    __syncthreads();
    for (int st = 128; st > 0; st >>= 1) {
        if (tid < st) red[tid] += red[tid + st];
        __syncthreads();
    }
    if (tid == 0) {
        float m = (float)(g_loss * (1.0 / 33554432.0));   // mean((q-in)^2)
        out[out_size - 2] = m + 0.25f * m;                // q_latent + COMMIT*e_latent
        out[out_size - 1] = expf(-red[0]);
    }
}

// ---------------- launch ----------------
extern "C" void kernel_launch(void* const* d_in, const int* in_sizes, int n_in,
                              void* d_out, int out_size) {
    const float* inputs = (const float*)d_in[0];
    const float* emb    = (const float*)d_in[1];
    const float* W_in   = (const float*)d_in[2];
    const float* b_in   = (const float*)d_in[3];
    const float* W_out  = (const float*)d_in[4];
    const float* b_out  = (const float*)d_in[5];
    float* out = (float*)d_out;

    cudaFuncSetAttribute(k_argmin, cudaFuncAttributeMaxDynamicSharedMemorySize, 66048);

    k_init<<<16, 256>>>();
    k_codes<<<NEMB / 16, 256>>>(emb, W_out, b_out);
    k_argmin<<<N_ROWS / TILE_M, 256, 66048>>>(inputs, W_in, b_in, emb);
    k_gather<<<8192, 256>>>(inputs, out);
    k_final<<<1, 256>>>(out, out_size);
}

// round 4
// speedup vs baseline: 2.9664x; 2.9662x over previous
#include <cuda_runtime.h>
#include <cuda_fp16.h>
#include <math.h>
#include <stdint.h>

#define N_ROWS 65536
#define IN_DIM 512
#define NEMB 4096
#define TILE_M 128

__device__ float  g_Qcodes[NEMB * IN_DIM];
__device__ float  g_ehalf[NEMB];
__device__ __half g_emb_f16[NEMB * 64];
__device__ int    g_idx[N_ROWS];
__device__ int    g_counts[NEMB];
__device__ double g_loss;

// ---- smem layout (bytes from dynamic base) ----
#define SM_XA  0        // x fp16 (negated) [128][72]  -> 18432
#define SM_B0  18432    // codes buf0 [128][72] fp16   -> 18432
#define SM_B1  36864    // codes buf1                  -> 18432
#define SM_XP  55296    // x fp32 [128][68]            -> 34816
#define DYN_SMEM 90112

__device__ __forceinline__ uint32_t smem_u32(const void* p) {
    uint32_t a;
    asm("{ .reg .u64 t; cvta.to.shared.u64 t, %1; cvt.u32.u64 %0, t; }" : "=r"(a) : "l"(p));
    return a;
}
__device__ __forceinline__ void ldmx4(uint32_t r[4], uint32_t addr) {
    asm volatile("ldmatrix.sync.aligned.m8n8.x4.shared.b16 {%0,%1,%2,%3}, [%4];"
        : "=r"(r[0]), "=r"(r[1]), "=r"(r[2]), "=r"(r[3]) : "r"(addr));
}
__device__ __forceinline__ void mma16816(float d[4], const uint32_t a[4], const uint32_t b[2]) {
    asm volatile("mma.sync.aligned.m16n8k16.row.col.f32.f16.f16.f32 "
        "{%0,%1,%2,%3}, {%4,%5,%6,%7}, {%8,%9}, {%0,%1,%2,%3};"
        : "+f"(d[0]), "+f"(d[1]), "+f"(d[2]), "+f"(d[3])
        : "r"(a[0]), "r"(a[1]), "r"(a[2]), "r"(a[3]), "r"(b[0]), "r"(b[1]));
}
// pack a 12-bit code index into the low mantissa bits of the fp32 score
__device__ __forceinline__ float packf(float s, int idx) {
    return __uint_as_float((__float_as_uint(s) & 0xFFFFF000u) | (uint32_t)idx);
}

__global__ void k_init() {
    int t = blockIdx.x * blockDim.x + threadIdx.x;
    if (t < NEMB) g_counts[t] = 0;
    if (t == 0) g_loss = 0.0;
}

__global__ void k_codes(const float* __restrict__ emb, const float* __restrict__ W_out,
                        const float* __restrict__ b_out) {
    __shared__ float es[16 * 64];
    int tid = threadIdx.x;
    int cb = blockIdx.x * 16;
    for (int i = tid; i < 16 * 64; i += 256) es[i] = emb[(size_t)cb * 64 + i];
    __syncthreads();
    if (tid < 16) {
        float s = 0.f;
        for (int k = 0; k < 64; k++) { float e = es[tid * 64 + k]; s = fmaf(e, e, s); }
        g_ehalf[cb + tid] = 0.5f * s;
    }
    for (int i = tid; i < 16 * 64; i += 256)
        g_emb_f16[(size_t)cb * 64 + i] = __float2half(es[i]);
    float ax[16], ay[16];
#pragma unroll
    for (int c = 0; c < 16; c++) { ax[c] = 0.f; ay[c] = 0.f; }
    int c0 = tid * 2;
    for (int k = 0; k < 64; k++) {
        float2 w = *(const float2*)&W_out[(size_t)k * 512 + c0];
#pragma unroll
        for (int c = 0; c < 16; c++) {
            float e = es[c * 64 + k];
            ax[c] = fmaf(e, w.x, ax[c]);
            ay[c] = fmaf(e, w.y, ay[c]);
        }
    }
    float2 b = *(const float2*)&b_out[c0];
#pragma unroll
    for (int c = 0; c < 16; c++)
        *(float2*)&g_Qcodes[(size_t)(cb + c) * 512 + c0] = make_float2(ax[c] + b.x, ay[c] + b.y);
}

__global__ __launch_bounds__(256, 2) void k_argmin_mma(
    const float* __restrict__ inputs, const float* __restrict__ W_in,
    const float* __restrict__ b_in, const float* __restrict__ emb) {
    extern __shared__ char sm[];
    uint32_t sb = smem_u32(sm);
    int tid = threadIdx.x;
    int wid = tid >> 5;
    int lane = tid & 31;
    int rowbase = blockIdx.x * TILE_M;

    // ======== Phase A: exact fp32 x = inputs_tile @ W_in + b_in ========
    float* in_sT = (float*)(sm + SM_B0);   // [64][128] fp32, spans B0+B1
    float* w_s   = (float*)(sm + SM_XP);   // [64][64]
    int rg = tid >> 4, cg = tid & 15;
    int lr = tid >> 1, loff = (tid & 1) * 32;
    float accA[8][4];
#pragma unroll
    for (int i = 0; i < 8; i++)
#pragma unroll
        for (int j = 0; j < 4; j++) accA[i][j] = 0.f;

    for (int kc = 0; kc < 8; kc++) {
        __syncthreads();
        const float4* gi = (const float4*)(inputs + (size_t)(rowbase + lr) * 512 + kc * 64 + loff);
#pragma unroll
        for (int i = 0; i < 8; i++) {
            float4 v = gi[i];
            int k = loff + i * 4;
            in_sT[(k + 0) * 128 + lr] = v.x;
            in_sT[(k + 1) * 128 + lr] = v.y;
            in_sT[(k + 2) * 128 + lr] = v.z;
            in_sT[(k + 3) * 128 + lr] = v.w;
        }
        const float4* gw = (const float4*)(W_in + (size_t)kc * 4096);
        float4* w4 = (float4*)w_s;
        for (int i = tid; i < 1024; i += 256) w4[i] = gw[i];
        __syncthreads();
#pragma unroll 4
        for (int k = 0; k < 64; k++) {
            float4 xa4 = *(const float4*)&in_sT[k * 128 + rg * 8];
            float4 xb4 = *(const float4*)&in_sT[k * 128 + rg * 8 + 4];
            float4 w  = *(const float4*)&w_s[k * 64 + cg * 4];
            float xs[8] = {xa4.x, xa4.y, xa4.z, xa4.w, xb4.x, xb4.y, xb4.z, xb4.w};
            float ws[4] = {w.x, w.y, w.z, w.w};
#pragma unroll
            for (int i = 0; i < 8; i++)
#pragma unroll
                for (int j = 0; j < 4; j++) accA[i][j] = fmaf(xs[i], ws[j], accA[i][j]);
        }
    }
    __syncthreads();   // in_sT / w_s dead
    {
        float4 b4 = *(const float4*)&b_in[cg * 4];
        float bs[4] = {b4.x, b4.y, b4.z, b4.w};
        float* x_p = (float*)(sm + SM_XP);
        __half* xa = (__half*)(sm + SM_XA);
#pragma unroll
        for (int i = 0; i < 8; i++) {
            int row = rg * 8 + i;
            float v0 = accA[i][0] + bs[0], v1 = accA[i][1] + bs[1];
            float v2 = accA[i][2] + bs[2], v3 = accA[i][3] + bs[3];
            x_p[row * 68 + cg * 4 + 0] = v0;
            x_p[row * 68 + cg * 4 + 1] = v1;
            x_p[row * 68 + cg * 4 + 2] = v2;
            x_p[row * 68 + cg * 4 + 3] = v3;
            // negated fp16 copy for MMA A operand (score = -x.e accumulates directly)
            __half2* dst = (__half2*)&xa[row * 72 + cg * 4];
            dst[0] = __floats2half2_rn(-v0, -v1);
            dst[1] = __floats2half2_rn(-v2, -v3);
        }
    }
    // stage codes chunk 0 -> B0
    {
        int code = tid >> 1, half = tid & 1;
        const uint4* gsrc = (const uint4*)(g_emb_f16 + (size_t)code * 64 + half * 32);
        uint4* sdst = (uint4*)(sm + SM_B0 + code * 144 + half * 64);
#pragma unroll
        for (int j = 0; j < 4; j++) sdst[j] = gsrc[j];
    }
    __syncthreads();

    // ======== Phase B: fp16 MMA screen over 32 chunks of 128 codes ========
    // A fragments (rows wid*16..+15, K=64): 4 k-steps, ldmatrix.x4 each
    uint32_t A[4][4];
    {
        int a_row = (lane & 7) + (lane & 8);
        int a_k8 = ((lane >> 4) & 1) * 8;
        uint32_t a0 = sb + SM_XA + (uint32_t)(wid * 16 + a_row) * 144 + a_k8 * 2;
#pragma unroll
        for (int k = 0; k < 4; k++) ldmx4(A[k], a0 + k * 32);
    }
    int b_row = (lane & 7) + ((lane >> 4) & 1) * 8;
    int b_k8 = ((lane >> 3) & 1) * 8;
    uint32_t b_lane_off = (uint32_t)b_row * 144 + b_k8 * 2;
    uint32_t bb0 = sb + SM_B0 + b_lane_off;
    uint32_t bb1 = sb + SM_B1 + b_lane_off;

    float pk0 = __uint_as_float(0x7F000000u);   // packed running min, row r
    float pk1 = __uint_as_float(0x7F000000u);   // row r+8

    for (int i = 0; i < 32; i++) {
        // prefetch next chunk (LDG early, STS after compute)
        uint4 pf0, pf1, pf2, pf3;
        bool havepf = (i + 1) < 32;
        int code = tid >> 1, half = tid & 1;
        if (havepf) {
            const uint4* gsrc = (const uint4*)(g_emb_f16 + (size_t)((i + 1) * 128 + code) * 64 + half * 32);
            pf0 = gsrc[0]; pf1 = gsrc[1]; pf2 = gsrc[2]; pf3 = gsrc[3];
        }
        uint32_t bb = (i & 1) ? bb1 : bb0;
        int idxbase = i * 128 + (lane & 3) * 2;
#pragma unroll
        for (int np = 0; np < 8; np++) {
            float d0[4] = {0.f, 0.f, 0.f, 0.f};
            float d1[4] = {0.f, 0.f, 0.f, 0.f};
            uint32_t baddr = bb + (uint32_t)np * (16 * 144);
#pragma unroll
            for (int k = 0; k < 4; k++) {
                uint32_t B[4];
                ldmx4(B, baddr + k * 32);
                mma16816(d0, A[k], B + 0);
                mma16816(d1, A[k], B + 2);
            }
            int c0 = idxbase + np * 16;
            int c1 = c0 + 8;
            pk0 = fminf(pk0, packf(d0[0], c0));
            pk0 = fminf(pk0, packf(d0[1], c0 + 1));
            pk1 = fminf(pk1, packf(d0[2], c0));
            pk1 = fminf(pk1, packf(d0[3], c0 + 1));
            pk0 = fminf(pk0, packf(d1[0], c1));
            pk0 = fminf(pk0, packf(d1[1], c1 + 1));
            pk1 = fminf(pk1, packf(d1[2], c1));
            pk1 = fminf(pk1, packf(d1[3], c1 + 1));
        }
        if (havepf) {
            uint4* sdst = (uint4*)(sm + ((i & 1) ? SM_B0 : SM_B1) + code * 144 + half * 64);
            sdst[0] = pf0; sdst[1] = pf1; sdst[2] = pf2; sdst[3] = pf3;
        }
        __syncthreads();
    }

    // ======== fp32 rescore of 4 lane-candidates per row + reduce ========
    {
        const float* x_p = (const float*)(sm + SM_XP);
        int r0 = wid * 16 + (lane >> 2);
#pragma unroll
        for (int h = 0; h < 2; h++) {
            int row = r0 + h * 8;
            int c = (int)(__float_as_uint(h ? pk1 : pk0) & 0xFFFu);
            const float4* e4 = (const float4*)(emb + (size_t)c * 64);
            const float4* x4 = (const float4*)(x_p + row * 68);
            float acc = 0.f;
#pragma unroll
            for (int d4 = 0; d4 < 16; d4++) {
                float4 e = e4[d4];
                float4 xv = x4[d4];
                acc = fmaf(xv.x, e.x, acc);
                acc = fmaf(xv.y, e.y, acc);
                acc = fmaf(xv.z, e.z, acc);
                acc = fmaf(xv.w, e.w, acc);
            }
            float s = __ldg(&g_ehalf[c]) - acc;
#pragma unroll
            for (int off = 1; off <= 2; off <<= 1) {
                float os = __shfl_xor_sync(0xffffffffu, s, off);
                int oc = __shfl_xor_sync(0xffffffffu, c, off);
                if (os < s || (os == s && oc < c)) { s = os; c = oc; }
            }
            if ((lane & 3) == 0) {
                g_idx[rowbase + row] = c;
                atomicAdd(&g_counts[c], 1);
            }
        }
    }
}

__global__ void k_gather(const float* __restrict__ inputs, float* __restrict__ out) {
    const int nf4 = N_ROWS * IN_DIM / 4;
    float lsum = 0.f;
    const float4* in4 = (const float4*)inputs;
    float4* out4 = (float4*)out;
    const float4* q4p = (const float4*)g_Qcodes;
    for (int f = blockIdx.x * blockDim.x + threadIdx.x; f < nf4; f += gridDim.x * blockDim.x) {
        int row = f >> 7;
        int col = f & 127;
        int id = __ldg(&g_idx[row]);
        float4 q = q4p[(size_t)id * 128 + col];
        float4 a = in4[f];
        float dx = q.x - a.x, dy = q.y - a.y, dz = q.z - a.z, dw = q.w - a.w;
        out4[f] = make_float4(a.x + dx, a.y + dy, a.z + dz, a.w + dw);
        lsum = fmaf(dx, dx, fmaf(dy, dy, fmaf(dz, dz, fmaf(dw, dw, lsum))));
    }
    for (int o = 16; o > 0; o >>= 1) lsum += __shfl_down_sync(0xffffffffu, lsum, o);
    __shared__ float ws[8];
    int lane = threadIdx.x & 31, w = threadIdx.x >> 5;
    if (lane == 0) ws[w] = lsum;
    __syncthreads();
    if (w == 0) {
        float v = (lane < 8) ? ws[lane] : 0.f;
        for (int o = 4; o > 0; o >>= 1) v += __shfl_down_sync(0xffffffffu, v, o);
        if (lane == 0) atomicAdd(&g_loss, (double)v);
    }
}

__global__ void k_final(float* __restrict__ out, int out_size) {
    __shared__ float red[256];
    int tid = threadIdx.x;
    float s = 0.f;
    for (int i = tid; i < NEMB; i += 256) {
        float p = (float)g_counts[i] * (1.0f / 65536.0f);
        s += p * logf(p + 1e-10f);
    }
    red[tid] = s;
    __syncthreads();
    for (int st = 128; st > 0; st >>= 1) {
        if (tid < st) red[tid] += red[tid + st];
        __syncthreads();
    }
    if (tid == 0) {
        float m = (float)(g_loss * (1.0 / 33554432.0));
        out[out_size - 2] = m + 0.25f * m;
        out[out_size - 1] = expf(-red[0]);
    }
}

extern "C" void kernel_launch(void* const* d_in, const int* in_sizes, int n_in,
                              void* d_out, int out_size) {
    const float* inputs = (const float*)d_in[0];
    const float* emb    = (const float*)d_in[1];
    const float* W_in   = (const float*)d_in[2];
    const float* b_in   = (const float*)d_in[3];
    const float* W_out  = (const float*)d_in[4];
    const float* b_out  = (const float*)d_in[5];
    float* out = (float*)d_out;

    cudaFuncSetAttribute(k_argmin_mma, cudaFuncAttributeMaxDynamicSharedMemorySize, DYN_SMEM);

    k_init<<<16, 256>>>();
    k_codes<<<NEMB / 16, 256>>>(emb, W_out, b_out);
    k_argmin_mma<<<N_ROWS / TILE_M, 256, DYN_SMEM>>>(inputs, W_in, b_in, emb);
    k_gather<<<8192, 256>>>(inputs, out);
    k_final<<<1, 256>>>(out, out_size);
}

// round 5
// speedup vs baseline: 3.0128x; 1.0156x over previous
#include <cuda_runtime.h>
#include <cuda_fp16.h>
#include <math.h>
#include <stdint.h>

#define N_ROWS 65536
#define IN_DIM 512
#define NEMB 4096
#define TILE_M 64

__device__ float  g_Qcodes[NEMB * IN_DIM];
__device__ float  g_ehalf[NEMB];
__device__ __half g_emb_f16[NEMB * 64];
__device__ __half g_WinT[64 * 512];          // W_in transposed [n][k], fp16
__device__ int    g_idx[N_ROWS];
__device__ int    g_counts[NEMB];
__device__ double g_loss;

// ---- smem layout (bytes from dynamic base) ----
#define SM_B0  0        // codes buf0 [128 codes][72 halfs] pitch 144B -> 18432 ; also W' [64][136h] in phase A
#define SM_B1  18432    // codes buf1 -> 18432
#define SM_XP  36864    // x fp32 [64][68] pitch 272B -> 17408 ; also A' fp16 [64][136h] in phase A
#define DYN_SMEM 54528

__device__ __forceinline__ uint32_t smem_u32(const void* p) {
    uint32_t a;
    asm("{ .reg .u64 t; cvta.to.shared.u64 t, %1; cvt.u32.u64 %0, t; }" : "=r"(a) : "l"(p));
    return a;
}
__device__ __forceinline__ void ldmx4(uint32_t r[4], uint32_t addr) {
    asm volatile("ldmatrix.sync.aligned.m8n8.x4.shared.b16 {%0,%1,%2,%3}, [%4];"
        : "=r"(r[0]), "=r"(r[1]), "=r"(r[2]), "=r"(r[3]) : "r"(addr));
}
__device__ __forceinline__ void mma16816(float d[4], const uint32_t a[4], const uint32_t b[2]) {
    asm volatile("mma.sync.aligned.m16n8k16.row.col.f32.f16.f16.f32 "
        "{%0,%1,%2,%3}, {%4,%5,%6,%7}, {%8,%9}, {%0,%1,%2,%3};"
        : "+f"(d[0]), "+f"(d[1]), "+f"(d[2]), "+f"(d[3])
        : "r"(a[0]), "r"(a[1]), "r"(a[2]), "r"(a[3]), "r"(b[0]), "r"(b[1]));
}
__device__ __forceinline__ float packf(float s, int idx) {
    return __uint_as_float((__float_as_uint(s) & 0xFFFFF000u) | (uint32_t)idx);
}
__device__ __forceinline__ uint32_t h2(float a, float b) {
    __half2 h = __floats2half2_rn(a, b);
    return *(uint32_t*)&h;
}

// ---- k_prep: zero accumulators + build W_in^T fp16 ----
__global__ void k_prep(const float* __restrict__ W_in) {
    int t = blockIdx.x * blockDim.x + threadIdx.x;   // 32768 threads
    if (t < NEMB) g_counts[t] = 0;
    if (t == 0) g_loss = 0.0;
    int n = t >> 9, k = t & 511;
    g_WinT[t] = __float2half(W_in[k * 64 + n]);
}

// ---- k_codes: Qcodes = emb@W_out + b_out; ehalf; emb fp16 ----
__global__ void k_codes(const float* __restrict__ emb, const float* __restrict__ W_out,
                        const float* __restrict__ b_out) {
    __shared__ float es[16 * 64];
    int tid = threadIdx.x;
    int cb = blockIdx.x * 16;
    for (int i = tid; i < 16 * 64; i += 256) es[i] = emb[(size_t)cb * 64 + i];
    __syncthreads();
    if (tid < 16) {
        float s = 0.f;
        for (int k = 0; k < 64; k++) { float e = es[tid * 64 + k]; s = fmaf(e, e, s); }
        g_ehalf[cb + tid] = 0.5f * s;
    }
    for (int i = tid; i < 16 * 64; i += 256)
        g_emb_f16[(size_t)cb * 64 + i] = __float2half(es[i]);
    float ax[16], ay[16];
#pragma unroll
    for (int c = 0; c < 16; c++) { ax[c] = 0.f; ay[c] = 0.f; }
    int c0 = tid * 2;
    for (int k = 0; k < 64; k++) {
        float2 w = *(const float2*)&W_out[(size_t)k * 512 + c0];
#pragma unroll
        for (int c = 0; c < 16; c++) {
            float e = es[c * 64 + k];
            ax[c] = fmaf(e, w.x, ax[c]);
            ay[c] = fmaf(e, w.y, ay[c]);
        }
    }
    float2 b = *(const float2*)&b_out[c0];
#pragma unroll
    for (int c = 0; c < 16; c++)
        *(float2*)&g_Qcodes[(size_t)(cb + c) * 512 + c0] = make_float2(ax[c] + b.x, ay[c] + b.y);
}

// ---- k_argmin2: 64-row tile, 128 threads ----
__global__ __launch_bounds__(128, 4) void k_argmin2(
    const float* __restrict__ inputs, const float* __restrict__ b_in,
    const float* __restrict__ emb) {
    extern __shared__ char sm[];
    uint32_t sb = smem_u32(sm);
    int tid = threadIdx.x;
    int wid = tid >> 5;
    int lane = tid & 31;
    int rowbase = blockIdx.x * TILE_M;

    // ldmatrix lane addressing (A: 16-row tiles; B: n/k col layout)
    int a_row = (lane & 7) + (lane & 8);
    int a_k8 = ((lane >> 4) & 1) * 8;
    int b_row = (lane & 7) + ((lane >> 4) & 1) * 8;
    int b_k8 = ((lane >> 3) & 1) * 8;

    // ======== Phase A: x[64][64] = inputs_tile @ W_in + b_in via fp16 MMA ========
    float d[8][4];
#pragma unroll
    for (int nt = 0; nt < 8; nt++)
#pragma unroll
        for (int j = 0; j < 4; j++) d[nt][j] = 0.f;

    int lrow = tid >> 1, lkh = tid & 1;   // loader: 2 threads per row
    for (int kc = 0; kc < 4; kc++) {
        __syncthreads();
        // A' chunk: inputs fp32 -> fp16 [64 rows][128 k] pitch 272B at SM_XP
        {
            const float4* gi = (const float4*)(inputs + (size_t)(rowbase + lrow) * 512 + kc * 128 + lkh * 64);
            char* adst = sm + SM_XP + lrow * 272 + lkh * 128;
#pragma unroll
            for (int j = 0; j < 8; j++) {
                float4 v0 = gi[2 * j], v1 = gi[2 * j + 1];
                uint4 u = make_uint4(h2(v0.x, v0.y), h2(v0.z, v0.w), h2(v1.x, v1.y), h2(v1.z, v1.w));
                *(uint4*)(adst + j * 16) = u;
            }
        }
        // W' chunk: g_WinT [64 n][512 k] slice -> [64][128] pitch 272B at SM_B0
        {
            const uint4* gw = (const uint4*)(g_WinT + (size_t)lrow * 512 + kc * 128 + lkh * 64);
            char* wdst = sm + SM_B0 + lrow * 272 + lkh * 128;
#pragma unroll
            for (int j = 0; j < 8; j++) *(uint4*)(wdst + j * 16) = gw[j];
        }
        __syncthreads();
        uint32_t abase = sb + SM_XP + (uint32_t)(wid * 16 + a_row) * 272 + a_k8 * 2;
        uint32_t bbase = sb + SM_B0 + (uint32_t)b_row * 272 + b_k8 * 2;
#pragma unroll
        for (int ks = 0; ks < 8; ks++) {
            uint32_t Af[4];
            ldmx4(Af, abase + ks * 32);
#pragma unroll
            for (int ng = 0; ng < 4; ng++) {
                uint32_t Bf[4];
                ldmx4(Bf, bbase + (uint32_t)ng * (16 * 272) + ks * 32);
                mma16816(d[ng * 2], Af, Bf + 0);
                mma16816(d[ng * 2 + 1], Af, Bf + 2);
            }
        }
    }
    __syncthreads();   // A'/W' regions now dead

    // bias add; store fp32 x to SM_XP; build negated fp16 A-frags in regs
    uint32_t A[4][4];
    {
        float* x_p = (float*)(sm + SM_XP);
        int r0 = wid * 16 + (lane >> 2);
#pragma unroll
        for (int nt = 0; nt < 8; nt++) {
            float2 bv = *(const float2*)&b_in[nt * 8 + (lane & 3) * 2];
            d[nt][0] += bv.x; d[nt][1] += bv.y;
            d[nt][2] += bv.x; d[nt][3] += bv.y;
            *(float2*)&x_p[r0 * 68 + nt * 8 + (lane & 3) * 2] = make_float2(d[nt][0], d[nt][1]);
            *(float2*)&x_p[(r0 + 8) * 68 + nt * 8 + (lane & 3) * 2] = make_float2(d[nt][2], d[nt][3]);
        }
#pragma unroll
        for (int ks = 0; ks < 4; ks++) {
            A[ks][0] = h2(-d[2 * ks][0], -d[2 * ks][1]);
            A[ks][1] = h2(-d[2 * ks][2], -d[2 * ks][3]);
            A[ks][2] = h2(-d[2 * ks + 1][0], -d[2 * ks + 1][1]);
            A[ks][3] = h2(-d[2 * ks + 1][2], -d[2 * ks + 1][3]);
        }
    }
    // stage codes chunk 0 -> B0 (1 thread per code)
    {
        const uint4* gsrc = (const uint4*)(g_emb_f16 + (size_t)tid * 64);
        char* sdst = sm + SM_B0 + tid * 144;
#pragma unroll
        for (int j = 0; j < 8; j++) *(uint4*)(sdst + j * 16) = gsrc[j];
    }
    __syncthreads();

    // ======== Screen: 32 chunks of 128 codes ========
    uint32_t b_lane_off = (uint32_t)b_row * 144 + b_k8 * 2;
    uint32_t bb0 = sb + SM_B0 + b_lane_off;
    uint32_t bb1 = sb + SM_B1 + b_lane_off;
    float pk0 = __uint_as_float(0x7F000000u);
    float pk1 = __uint_as_float(0x7F000000u);

    for (int i = 0; i < 32; i++) {
        uint4 pf[8];
        bool havepf = (i + 1) < 32;
        if (havepf) {
            const uint4* gsrc = (const uint4*)(g_emb_f16 + (size_t)((i + 1) * 128 + tid) * 64);
#pragma unroll
            for (int j = 0; j < 8; j++) pf[j] = gsrc[j];
        }
        uint32_t bb = (i & 1) ? bb1 : bb0;
        int idxbase = i * 128 + (lane & 3) * 2;
#pragma unroll
        for (int np = 0; np < 8; np++) {
            float d0[4] = {0.f, 0.f, 0.f, 0.f};
            float d1[4] = {0.f, 0.f, 0.f, 0.f};
            uint32_t baddr = bb + (uint32_t)np * (16 * 144);
#pragma unroll
            for (int k = 0; k < 4; k++) {
                uint32_t B[4];
                ldmx4(B, baddr + k * 32);
                mma16816(d0, A[k], B + 0);
                mma16816(d1, A[k], B + 2);
            }
            int c0 = idxbase + np * 16;
            int c1 = c0 + 8;
            pk0 = fminf(pk0, packf(d0[0], c0));
            pk0 = fminf(pk0, packf(d0[1], c0 + 1));
            pk1 = fminf(pk1, packf(d0[2], c0));
            pk1 = fminf(pk1, packf(d0[3], c0 + 1));
            pk0 = fminf(pk0, packf(d1[0], c1));
            pk0 = fminf(pk0, packf(d1[1], c1 + 1));
            pk1 = fminf(pk1, packf(d1[2], c1));
            pk1 = fminf(pk1, packf(d1[3], c1 + 1));
        }
        if (havepf) {
            char* sdst = sm + ((i & 1) ? SM_B0 : SM_B1) + tid * 144;
#pragma unroll
            for (int j = 0; j < 8; j++) *(uint4*)(sdst + j * 16) = pf[j];
        }
        __syncthreads();
    }

    // ======== exact fp32 rescore of 4 lane-candidates per row ========
    {
        const float* x_p = (const float*)(sm + SM_XP);
        int r0 = wid * 16 + (lane >> 2);
#pragma unroll
        for (int h = 0; h < 2; h++) {
            int row = r0 + h * 8;
            int c = (int)(__float_as_uint(h ? pk1 : pk0) & 0xFFFu);
            const float4* e4 = (const float4*)(emb + (size_t)c * 64);
            const float4* x4 = (const float4*)(x_p + row * 68);
            float acc = 0.f;
#pragma unroll
            for (int d4 = 0; d4 < 16; d4++) {
                float4 e = e4[d4];
                float4 xv = x4[d4];
                acc = fmaf(xv.x, e.x, acc);
                acc = fmaf(xv.y, e.y, acc);
                acc = fmaf(xv.z, e.z, acc);
                acc = fmaf(xv.w, e.w, acc);
            }
            float s = __ldg(&g_ehalf[c]) - acc;
#pragma unroll
            for (int off = 1; off <= 2; off <<= 1) {
                float os = __shfl_xor_sync(0xffffffffu, s, off);
                int oc = __shfl_xor_sync(0xffffffffu, c, off);
                if (os < s || (os == s && oc < c)) { s = os; c = oc; }
            }
            if ((lane & 3) == 0) {
                g_idx[rowbase + row] = c;
                atomicAdd(&g_counts[c], 1);
            }
        }
    }
}

__global__ void k_gather(const float* __restrict__ inputs, float* __restrict__ out) {
    const int nf4 = N_ROWS * IN_DIM / 4;
    float lsum = 0.f;
    const float4* in4 = (const float4*)inputs;
    float4* out4 = (float4*)out;
    const float4* q4p = (const float4*)g_Qcodes;
    for (int f = blockIdx.x * blockDim.x + threadIdx.x; f < nf4; f += gridDim.x * blockDim.x) {
        int row = f >> 7;
        int col = f & 127;
        int id = __ldg(&g_idx[row]);
        float4 q = q4p[(size_t)id * 128 + col];
        float4 a = in4[f];
        float dx = q.x - a.x, dy = q.y - a.y, dz = q.z - a.z, dw = q.w - a.w;
        out4[f] = make_float4(a.x + dx, a.y + dy, a.z + dz, a.w + dw);
        lsum = fmaf(dx, dx, fmaf(dy, dy, fmaf(dz, dz, fmaf(dw, dw, lsum))));
    }
    for (int o = 16; o > 0; o >>= 1) lsum += __shfl_down_sync(0xffffffffu, lsum, o);
    __shared__ float ws[8];
    int lane = threadIdx.x & 31, w = threadIdx.x >> 5;
    if (lane == 0) ws[w] = lsum;
    __syncthreads();
    if (w == 0) {
        float v = (lane < 8) ? ws[lane] : 0.f;
        for (int o = 4; o > 0; o >>= 1) v += __shfl_down_sync(0xffffffffu, v, o);
        if (lane == 0) atomicAdd(&g_loss, (double)v);
    }
}

__global__ void k_final(float* __restrict__ out, int out_size) {
    __shared__ float red[256];
    int tid = threadIdx.x;
    float s = 0.f;
    for (int i = tid; i < NEMB; i += 256) {
        float p = (float)g_counts[i] * (1.0f / 65536.0f);
        s += p * logf(p + 1e-10f);
    }
    red[tid] = s;
    __syncthreads();
    for (int st = 128; st > 0; st >>= 1) {
        if (tid < st) red[tid] += red[tid + st];
        __syncthreads();
    }
    if (tid == 0) {
        float m = (float)(g_loss * (1.0 / 33554432.0));
        out[out_size - 2] = m + 0.25f * m;
        out[out_size - 1] = expf(-red[0]);
    }
}

extern "C" void kernel_launch(void* const* d_in, const int* in_sizes, int n_in,
                              void* d_out, int out_size) {
    const float* inputs = (const float*)d_in[0];
    const float* emb    = (const float*)d_in[1];
    const float* W_in   = (const float*)d_in[2];
    const float* b_in   = (const float*)d_in[3];
    const float* W_out  = (const float*)d_in[4];
    const float* b_out  = (const float*)d_in[5];
    float* out = (float*)d_out;

    cudaFuncSetAttribute(k_argmin2, cudaFuncAttributeMaxDynamicSharedMemorySize, DYN_SMEM);

    k_prep<<<128, 256>>>(W_in);
    k_codes<<<NEMB / 16, 256>>>(emb, W_out, b_out);
    k_argmin2<<<N_ROWS / TILE_M, 128, DYN_SMEM>>>(inputs, b_in, emb);
    k_gather<<<8192, 256>>>(inputs, out);
    k_final<<<1, 256>>>(out, out_size);
}